// round 13
// baseline (speedup 1.0000x reference)
#include <cuda_runtime.h>
#include <cuda_bf16.h>
#include <math.h>
#include <stdint.h>

// Geometry: point_1 (96000,3) feat_1 (96000,128); point_2 (24000,3)
// feat_2 (24000,256); B=8 -> 12000 queries / 3000 points per cloud.
#define B_CONST     8
#define N_TOT_MAX   96000
#define M_TOT_MAX   24000
#define OUTP        128
#define MP_MAX      1500      // point PAIRS per cloud

// ---------------- device scratch ------------------------------------------
__device__ float  g_f2[M_TOT_MAX * OUTP];
__device__ float4 g_ptsA[M_TOT_MAX / 2];
__device__ float4 g_ptsB[M_TOT_MAX / 2];
__device__ int    g_idx[N_TOT_MAX * 3];
__device__ float  g_w [N_TOT_MAX * 3];
// bf16 3-way splits of W, stored transposed: [split][n][k]
__device__ unsigned short g_w1s[3 * 128 * 128];   // W1: k=128
__device__ unsigned short g_w2s[3 * 128 * 256];   // W2: k=256

// ---------------- frozen numerics (bit-exact vs reference) ----------------
__device__ __forceinline__ float sq3(float x, float y, float z) {
    return __fmaf_rn(x, x, __fmaf_rn(y, y, __fmul_rn(z, z)));
}

// ---------------- packed f32x2 helpers ------------------------------------
__device__ __forceinline__ uint64_t bcast2(float v) {
    uint64_t r; uint32_t u = __float_as_uint(v);
    asm("mov.b64 %0, {%1, %1};" : "=l"(r) : "r"(u));
    return r;
}
__device__ __forceinline__ uint64_t mul2(uint64_t a, uint64_t b) {
    uint64_t d; asm("mul.rn.f32x2 %0, %1, %2;" : "=l"(d) : "l"(a), "l"(b));
    return d;
}
__device__ __forceinline__ uint64_t fma2(uint64_t a, uint64_t b, uint64_t c) {
    uint64_t d; asm("fma.rn.f32x2 %0, %1, %2, %3;" : "=l"(d) : "l"(a), "l"(b), "l"(c));
    return d;
}
__device__ __forceinline__ uint64_t add2(uint64_t a, uint64_t b) {
    uint64_t d; asm("add.rn.f32x2 %0, %1, %2;" : "=l"(d) : "l"(a), "l"(b));
    return d;
}
__device__ __forceinline__ void unpack2(uint64_t v, float& lo, float& hi) {
    asm("mov.b64 {%0, %1}, %2;" : "=f"(lo), "=f"(hi) : "l"(v));
}

// ---------------- pack points (negated-doubled pair layout) ---------------
__global__ void pack_pts_kernel(const float* __restrict__ p2, int m_pairs) {
    int i = blockIdx.x * blockDim.x + threadIdx.x;
    if (i < m_pairs) {
        float x0 = p2[6 * i + 0], y0 = p2[6 * i + 1], z0 = p2[6 * i + 2];
        float x1 = p2[6 * i + 3], y1 = p2[6 * i + 4], z1 = p2[6 * i + 5];
        g_ptsA[i] = make_float4(-2.0f * x0, -2.0f * x1, -2.0f * y0, -2.0f * y1);
        g_ptsB[i] = make_float4(-2.0f * z0, -2.0f * z1, sq3(x0, y0, z0), sq3(x1, y1, z1));
    }
}

// ---------------- exact 3-NN + IDW (f32x2, warp-balanced grid) ------------
// 8 batches x 47 blocks, 256 queries/block -> 8 active warps = 2 per SMSP
// (fixes the 6-warp wid%4 SMSP imbalance). Numerics byte-identical to the
// round-11 PASSING kernel (bit-exact selection).
__global__ void knn_kernel(const float* __restrict__ q_pts,
                           int n_per, int m_pairs, int bpb, int qpb) {
    __shared__ __align__(16) float4 spA[MP_MAX];
    __shared__ __align__(16) float4 spB[MP_MAX];
    int batch = blockIdx.x / bpb;
    int bb    = blockIdx.x % bpb;
    int tid = threadIdx.x;

    for (int i = tid; i < m_pairs; i += blockDim.x) {
        spA[i] = g_ptsA[batch * m_pairs + i];
        spB[i] = g_ptsB[batch * m_pairs + i];
    }
    __syncthreads();

    int ql = bb * qpb + tid;
    if (ql >= n_per) return;
    int qg = batch * n_per + ql;

    float qx = q_pts[3 * qg + 0];
    float qy = q_pts[3 * qg + 1];
    float qz = q_pts[3 * qg + 2];
    float qq = sq3(qx, qy, qz);

    uint64_t qx2 = bcast2(qx), qy2 = bcast2(qy), qz2 = bcast2(qz);
    uint64_t qq2 = bcast2(qq);

    uint32_t sA = (uint32_t)__cvta_generic_to_shared(spA);
    uint32_t sB = (uint32_t)__cvta_generic_to_shared(spB);

    float b0v = INFINITY, b1v = INFINITY, b2v = INFINITY;
    int   b0i = 0, b1i = 0, b2i = 0;

#pragma unroll 1
    for (int jp0 = 0; jp0 < m_pairs; jp0 += 4) {
        float dv[8];
        float cmin;
#pragma unroll
        for (int u = 0; u < 4; u++) {
            uint32_t off = (uint32_t)(jp0 + u) * 16u;
            uint64_t px2, py2, pz2, pw2;
            asm("ld.shared.v2.u64 {%0, %1}, [%2];"
                : "=l"(px2), "=l"(py2) : "r"(sA + off));
            asm("ld.shared.v2.u64 {%0, %1}, [%2];"
                : "=l"(pz2), "=l"(pw2) : "r"(sB + off));
            uint64_t dotn = fma2(qz2, pz2, fma2(qy2, py2, mul2(qx2, px2)));
            uint64_t t    = add2(qq2, pw2);
            uint64_t d    = add2(t, dotn);
            float dlo, dhi;
            unpack2(d, dlo, dhi);
            dv[2 * u]     = dlo;
            dv[2 * u + 1] = dhi;
            float m = fminf(dlo, dhi);
            cmin = (u == 0) ? m : fminf(cmin, m);
        }
        if (cmin < b2v) {
#pragma unroll
            for (int v = 0; v < 8; v++) {
                float d = dv[v];
                if (d < b2v) {
                    int j = jp0 * 2 + v;
                    if (d < b1v) {
                        b2v = b1v; b2i = b1i;
                        if (d < b0v) { b1v = b0v; b1i = b0i; b0v = d; b0i = j; }
                        else         { b1v = d;  b1i = j; }
                    } else {
                        b2v = d; b2i = j;
                    }
                }
            }
        }
    }

    float d0 = fmaxf(b0v, 0.0f);
    float d1 = fmaxf(b1v, 0.0f);
    float d2 = fmaxf(b2v, 0.0f);
    float r0 = __fdiv_rn(1.0f, __fadd_rn(d0, 1e-8f));
    float r1 = __fdiv_rn(1.0f, __fadd_rn(d1, 1e-8f));
    float r2 = __fdiv_rn(1.0f, __fadd_rn(d2, 1e-8f));
    float s = __fadd_rn(__fadd_rn(r0, r1), r2);
    int m_per = m_pairs * 2;
    g_w[qg * 3 + 0] = __fdiv_rn(r0, s);
    g_w[qg * 3 + 1] = __fdiv_rn(r1, s);
    g_w[qg * 3 + 2] = __fdiv_rn(r2, s);
    g_idx[qg * 3 + 0] = batch * m_per + b0i;
    g_idx[qg * 3 + 1] = batch * m_per + b1i;
    g_idx[qg * 3 + 2] = batch * m_per + b2i;
}

// ---------------- bf16 3-way split ----------------------------------------
__device__ __forceinline__ void bf16_split3(float v, unsigned short& a,
                                            unsigned short& b, unsigned short& c) {
    __nv_bfloat16 h0 = __float2bfloat16_rn(v);
    float r1 = v - __bfloat162float(h0);
    __nv_bfloat16 h1 = __float2bfloat16_rn(r1);
    float r2 = r1 - __bfloat162float(h1);
    __nv_bfloat16 h2 = __float2bfloat16_rn(r2);
    a = __bfloat16_as_ushort(h0);
    b = __bfloat16_as_ushort(h1);
    c = __bfloat16_as_ushort(h2);
}

// W split prepass: W[k][n] fp32 -> dst[i][n*K + k] bf16 (transposed)
__global__ void wsplit_kernel(const float* __restrict__ W, unsigned short* dst, int K) {
    int id = blockIdx.x * blockDim.x + threadIdx.x;
    int total = 128 * K;
    if (id < total) {
        int n = id / K, k = id % K;
        unsigned short a, b, c;
        bf16_split3(W[(size_t)k * 128 + n], a, b, c);
        dst[id] = a;
        dst[total + id] = b;
        dst[2 * total + id] = c;
    }
}

// ---------------- mma.sync tensor-core GEMM (portable PTX, sm_80+) --------
// D[row][col] = sum_k X[row][k] * W[k][col], bf16 3-split x 6 cross passes.
// CTA: 128 rows x 128 cols, 8 warps (warp = 32 rows x 64 cols).
// K-tile = 64. smem tiles: 3x A-split + 3x B-split, each 128 x 64 bf16 with
// 144B padded row stride (≡4 mod 32 banks -> conflict-free ldmatrix).
#define TILE_STRIDE_B 144
#define TILE_BYTES    (128 * TILE_STRIDE_B)   // 18432

__device__ __forceinline__ void ldm_x4(uint32_t addr, uint32_t& f0, uint32_t& f1,
                                       uint32_t& f2, uint32_t& f3) {
    asm volatile("ldmatrix.sync.aligned.m8n8.x4.shared.b16 {%0,%1,%2,%3}, [%4];"
                 : "=r"(f0), "=r"(f1), "=r"(f2), "=r"(f3) : "r"(addr));
}
__device__ __forceinline__ void mma_bf16(float* d, const uint32_t* a,
                                         uint32_t b0, uint32_t b1) {
    asm volatile(
        "mma.sync.aligned.m16n8k16.row.col.f32.bf16.bf16.f32 "
        "{%0,%1,%2,%3}, {%4,%5,%6,%7}, {%8,%9}, {%0,%1,%2,%3};"
        : "+f"(d[0]), "+f"(d[1]), "+f"(d[2]), "+f"(d[3])
        : "r"(a[0]), "r"(a[1]), "r"(a[2]), "r"(a[3]), "r"(b0), "r"(b1));
}

template <int KW, bool GATHER>
__global__ void __launch_bounds__(256, 2)
mma_gemm_kernel(const float* __restrict__ X, const unsigned short* __restrict__ Ws,
                const float* __restrict__ bb, const float* __restrict__ gg,
                const float* __restrict__ bet, const float* __restrict__ mu,
                const float* __restrict__ var, float* __restrict__ out, int M) {
    extern __shared__ __align__(16) char smem[];
    uint32_t smem_sh = (uint32_t)__cvta_generic_to_shared(smem);

    int tid  = threadIdx.x;
    int wid  = tid >> 5;
    int lane = tid & 31;
    int warp_m = wid & 3;          // 4 row-groups of 32
    int warp_n = wid >> 2;         // 2 col-groups of 64
    int m0 = blockIdx.x * 128;
    constexpr int KH = KW / 64;
    constexpr int WTOT = 128 * KW;

    float acc[2][8][4];            // [m16 tile][n8 tile][regs]
#pragma unroll
    for (int a = 0; a < 2; a++)
#pragma unroll
        for (int b = 0; b < 8; b++)
#pragma unroll
            for (int c = 0; c < 4; c++) acc[a][b][c] = 0.0f;

    // loader mapping: r = row 0..127, hf = k-half (32 bf16 each)
    int r  = tid >> 1;
    int hf = tid & 1;
    int arow = m0 + r; if (arow >= M) arow = M - 1;

    for (int kh = 0; kh < KH; kh++) {
        if (kh > 0) __syncthreads();

        // ---- W splits (pre-split bf16) -> tiles 3..5 ----
#pragma unroll
        for (int i = 0; i < 3; i++) {
            const unsigned short* src = Ws + (size_t)i * WTOT + (size_t)r * KW + kh * 64 + hf * 32;
            char* dst = smem + (3 + i) * TILE_BYTES + r * TILE_STRIDE_B + hf * 64;
#pragma unroll
            for (int j = 0; j < 4; j++)
                *reinterpret_cast<uint4*>(dst + j * 16) =
                    *reinterpret_cast<const uint4*>(src + j * 8);
        }
        // ---- X rows (fp32) -> split3 -> tiles 0..2 ----
        {
            const float* src = X + (size_t)arow * KW + kh * 64 + hf * 32;
            char* t0 = smem + 0 * TILE_BYTES + r * TILE_STRIDE_B + hf * 64;
            char* t1 = smem + 1 * TILE_BYTES + r * TILE_STRIDE_B + hf * 64;
            char* t2 = smem + 2 * TILE_BYTES + r * TILE_STRIDE_B + hf * 64;
#pragma unroll
            for (int g = 0; g < 4; g++) {
                float4 f0 = *reinterpret_cast<const float4*>(src + g * 8);
                float4 f1 = *reinterpret_cast<const float4*>(src + g * 8 + 4);
                float v[8] = {f0.x, f0.y, f0.z, f0.w, f1.x, f1.y, f1.z, f1.w};
                unsigned short a[8], b[8], c[8];
#pragma unroll
                for (int e = 0; e < 8; e++) bf16_split3(v[e], a[e], b[e], c[e]);
                uint4 pa, pb, pc;
                pa.x = (uint32_t)a[0] | ((uint32_t)a[1] << 16);
                pa.y = (uint32_t)a[2] | ((uint32_t)a[3] << 16);
                pa.z = (uint32_t)a[4] | ((uint32_t)a[5] << 16);
                pa.w = (uint32_t)a[6] | ((uint32_t)a[7] << 16);
                pb.x = (uint32_t)b[0] | ((uint32_t)b[1] << 16);
                pb.y = (uint32_t)b[2] | ((uint32_t)b[3] << 16);
                pb.z = (uint32_t)b[4] | ((uint32_t)b[5] << 16);
                pb.w = (uint32_t)b[6] | ((uint32_t)b[7] << 16);
                pc.x = (uint32_t)c[0] | ((uint32_t)c[1] << 16);
                pc.y = (uint32_t)c[2] | ((uint32_t)c[3] << 16);
                pc.z = (uint32_t)c[4] | ((uint32_t)c[5] << 16);
                pc.w = (uint32_t)c[6] | ((uint32_t)c[7] << 16);
                *reinterpret_cast<uint4*>(t0 + g * 16) = pa;
                *reinterpret_cast<uint4*>(t1 + g * 16) = pb;
                *reinterpret_cast<uint4*>(t2 + g * 16) = pc;
            }
        }
        __syncthreads();

        // ---- compute: 6 split passes ----
        // ldmatrix lane address: row-in-16 = lane&15, col-half = lane>>4
        int lrow = lane & 15;
        int lcol = (lane >> 4) * 8;
        const int AI[6] = {0, 0, 1, 0, 2, 1};
        const int BJ[6] = {0, 1, 0, 2, 0, 1};
#pragma unroll
        for (int p = 0; p < 6; p++) {
            uint32_t abase = smem_sh + AI[p] * TILE_BYTES;
            uint32_t bbase = smem_sh + (3 + BJ[p]) * TILE_BYTES;
#pragma unroll
            for (int kc = 0; kc < 4; kc++) {
                int kb = kc * 16 + lcol;
                uint32_t af[2][4];
#pragma unroll
                for (int mt = 0; mt < 2; mt++) {
                    uint32_t addr = abase
                        + (uint32_t)(warp_m * 32 + mt * 16 + lrow) * TILE_STRIDE_B
                        + (uint32_t)kb * 2;
                    ldm_x4(addr, af[mt][0], af[mt][1], af[mt][2], af[mt][3]);
                }
#pragma unroll
                for (int nt = 0; nt < 4; nt++) {
                    uint32_t addr = bbase
                        + (uint32_t)(warp_n * 64 + nt * 16 + lrow) * TILE_STRIDE_B
                        + (uint32_t)kb * 2;
                    uint32_t g0, g1, g2, g3;
                    ldm_x4(addr, g0, g1, g2, g3);
                    // (g0,g2) = n-sub0 frag, (g1,g3) = n-sub1 frag
#pragma unroll
                    for (int mt = 0; mt < 2; mt++) {
                        mma_bf16(acc[mt][nt * 2],     af[mt], g0, g2);
                        mma_bf16(acc[mt][nt * 2 + 1], af[mt], g1, g3);
                    }
                }
            }
        }
    }

    // ---- epilogue: BN + ReLU (+ gather), rows/cols from mma layout ----
    int lq = lane >> 2;            // 0..7
    int lr = lane & 3;             // col pair selector
    float S0[8], S1[8], T0[8], T1[8];
#pragma unroll
    for (int nt = 0; nt < 8; nt++) {
        int c = warp_n * 64 + nt * 8 + lr * 2;
        float sc0 = gg[c] * rsqrtf(var[c] + 1e-5f);
        float sc1 = gg[c + 1] * rsqrtf(var[c + 1] + 1e-5f);
        S0[nt] = sc0; T0[nt] = fmaf(bb[c] - mu[c], sc0, bet[c]);
        S1[nt] = sc1; T1[nt] = fmaf(bb[c + 1] - mu[c + 1], sc1, bet[c + 1]);
    }
#pragma unroll
    for (int mt = 0; mt < 2; mt++) {
#pragma unroll
        for (int h = 0; h < 2; h++) {
            int row = m0 + warp_m * 32 + mt * 16 + h * 8 + lq;
            if (row < M) {
                int   id0 = 0, id1 = 0, id2 = 0;
                float w0 = 0.f, w1 = 0.f, w2 = 0.f;
                if (GATHER) {
                    id0 = g_idx[row * 3 + 0]; w0 = g_w[row * 3 + 0];
                    id1 = g_idx[row * 3 + 1]; w1 = g_w[row * 3 + 1];
                    id2 = g_idx[row * 3 + 2]; w2 = g_w[row * 3 + 2];
                }
#pragma unroll
                for (int nt = 0; nt < 8; nt++) {
                    int col = warp_n * 64 + nt * 8 + lr * 2;
                    float y0 = fmaxf(fmaf(acc[mt][nt][h * 2],     S0[nt], T0[nt]), 0.0f);
                    float y1 = fmaxf(fmaf(acc[mt][nt][h * 2 + 1], S1[nt], T1[nt]), 0.0f);
                    if (GATHER) {
                        const float* f0p = g_f2 + (size_t)id0 * 128 + col;
                        const float* f1p = g_f2 + (size_t)id1 * 128 + col;
                        const float* f2p = g_f2 + (size_t)id2 * 128 + col;
                        y0 = fmaf(w0, f0p[0], y0); y1 = fmaf(w0, f0p[1], y1);
                        y0 = fmaf(w1, f1p[0], y0); y1 = fmaf(w1, f1p[1], y1);
                        y0 = fmaf(w2, f2p[0], y0); y1 = fmaf(w2, f2p[1], y1);
                    }
                    float2 o = make_float2(y0, y1);
                    *reinterpret_cast<float2*>(&out[(size_t)row * 128 + col]) = o;
                }
            }
        }
    }
}

// ---------------- launch --------------------------------------------------
extern "C" void kernel_launch(void* const* d_in, const int* in_sizes, int n_in,
                              void* d_out, int out_size) {
    const float* point1 = (const float*)d_in[0];
    const float* feat1  = (const float*)d_in[1];
    const float* point2 = (const float*)d_in[2];
    const float* feat2  = (const float*)d_in[3];
    const float* W1  = (const float*)d_in[4];
    const float* b1  = (const float*)d_in[5];
    const float* g1  = (const float*)d_in[6];
    const float* be1 = (const float*)d_in[7];
    const float* mu1 = (const float*)d_in[8];
    const float* v1  = (const float*)d_in[9];
    const float* W2  = (const float*)d_in[10];
    const float* b2  = (const float*)d_in[11];
    const float* g2  = (const float*)d_in[12];
    const float* be2 = (const float*)d_in[13];
    const float* mu2 = (const float*)d_in[14];
    const float* v2  = (const float*)d_in[15];

    int n_tot = in_sizes[0] / 3;           // 96000
    int m_tot = in_sizes[2] / 3;           // 24000
    int n_per = n_tot / B_CONST;           // 12000
    int m_pairs = (m_tot / B_CONST) / 2;   // 1500

    float* f2 = nullptr;
    cudaGetSymbolAddress((void**)&f2, g_f2);
    unsigned short *w1s = nullptr, *w2s = nullptr;
    cudaGetSymbolAddress((void**)&w1s, g_w1s);
    cudaGetSymbolAddress((void**)&w2s, g_w2s);

    const int SMEM_BYTES = 6 * TILE_BYTES;   // 110592
    cudaFuncSetAttribute(mma_gemm_kernel<256, false>,
                         cudaFuncAttributeMaxDynamicSharedMemorySize, SMEM_BYTES);
    cudaFuncSetAttribute(mma_gemm_kernel<128, true>,
                         cudaFuncAttributeMaxDynamicSharedMemorySize, SMEM_BYTES);

    // 1) pack coarse points
    int tot_pairs = m_tot / 2;
    pack_pts_kernel<<<(tot_pairs + 255) / 256, 256>>>(point2, tot_pairs);

    // 2) split weights to bf16 triples (transposed)
    wsplit_kernel<<<(128 * 128 + 255) / 256, 256>>>(W1, w1s, 128);
    wsplit_kernel<<<(128 * 256 + 255) / 256, 256>>>(W2, w2s, 256);

    // 3) dense2 + BN + ReLU -> g_f2  (mma.sync tensor core)
    mma_gemm_kernel<256, false><<<(m_tot + 127) / 128, 256, SMEM_BYTES>>>(
        feat2, w2s, b2, g2, be2, mu2, v2, f2, m_tot);

    // 4) exact 3-NN + IDW; 8 x 47 blocks, 256 q/block (8 balanced warps)
    int bpb = 47, qpb = 256;
    knn_kernel<<<B_CONST * bpb, 256>>>(point1, n_per, m_pairs, bpb, qpb);

    // 5) dense1 + BN + ReLU + gather-add -> out (mma.sync tensor core)
    mma_gemm_kernel<128, true><<<(n_tot + 127) / 128, 256, SMEM_BYTES>>>(
        feat1, w1s, b1, g1, be1, mu1, v1, (float*)d_out, n_tot);
}

// round 14
// speedup vs baseline: 1.3810x; 1.3810x over previous
#include <cuda_runtime.h>
#include <math.h>
#include <stdint.h>

// Geometry: point_1 (96000,3) feat_1 (96000,128); point_2 (24000,3)
// feat_2 (24000,256); B=8 -> 12000 queries / 3000 points per cloud.
#define B_CONST     8
#define N_TOT_MAX   96000
#define M_TOT_MAX   24000
#define OUTP        128
#define MP_MAX      1500      // point PAIRS per cloud

// ---------------- device scratch ------------------------------------------
__device__ float  g_f2[M_TOT_MAX * OUTP];
__device__ float4 g_ptsA[M_TOT_MAX / 2];   // (-2x0,-2x1,-2y0,-2y1)
__device__ float4 g_ptsB[M_TOT_MAX / 2];   // (-2z0,-2z1, pp0, pp1)
__device__ int    g_idx[N_TOT_MAX * 3];
__device__ float  g_w [N_TOT_MAX * 3];

// ---------------- frozen numerics (bit-exact vs reference) ----------------
__device__ __forceinline__ float sq3(float x, float y, float z) {
    return __fmaf_rn(x, x, __fmaf_rn(y, y, __fmul_rn(z, z)));
}

// ---------------- packed f32x2 helpers ------------------------------------
__device__ __forceinline__ uint64_t bcast2(float v) {
    uint64_t r; uint32_t u = __float_as_uint(v);
    asm("mov.b64 %0, {%1, %1};" : "=l"(r) : "r"(u));
    return r;
}
__device__ __forceinline__ uint64_t fma2(uint64_t a, uint64_t b, uint64_t c) {
    uint64_t d; asm("fma.rn.f32x2 %0, %1, %2, %3;" : "=l"(d) : "l"(a), "l"(b), "l"(c));
    return d;
}
__device__ __forceinline__ void unpack2(uint64_t v, float& lo, float& hi) {
    asm("mov.b64 {%0, %1}, %2;" : "=f"(lo), "=f"(hi) : "l"(v));
}

// ---------------- pack points (negated-doubled pair layout) ---------------
__global__ void pack_pts_kernel(const float* __restrict__ p2, int m_pairs) {
    int i = blockIdx.x * blockDim.x + threadIdx.x;
    if (i < m_pairs) {
        float x0 = p2[6 * i + 0], y0 = p2[6 * i + 1], z0 = p2[6 * i + 2];
        float x1 = p2[6 * i + 3], y1 = p2[6 * i + 4], z1 = p2[6 * i + 5];
        g_ptsA[i] = make_float4(-2.0f * x0, -2.0f * x1, -2.0f * y0, -2.0f * y1);
        g_ptsB[i] = make_float4(-2.0f * z0, -2.0f * z1, sq3(x0, y0, z0), sq3(x1, y1, z1));
    }
}

// ---------------- exact 3-NN + IDW: screened f32x2 scan -------------------
// Hot loop computes a SCREENING value per point pair:
//   d' = fma2(qz,pz', fma2(qy,py', fma2(qx,px', pp)))   (3 fma2; p' = -2p)
// and fires the rare path when  min(d') < thr = (b2v - qq) + 4e-6.
// |d' - (d_exact - qq)| <= 6 roundings of O(6) values <= 1.5e-6  << 4e-6,
// so no true candidate is ever missed. The rare path recomputes the FROZEN
// bit-exact scalar d and runs the frozen stable insert -> selection is
// bit-identical to the round-11 passing kernel.
// SMSP balance: 592 CTAs = 4/SM; active thread window rotates by 64 threads
// based on (blockIdx.x/148)&1 so co-resident CTAs place their 6 active warps
// on complementary SMSPs (6 warp-loops per SMSP instead of 8 on SMSP0).
__global__ void __launch_bounds__(256, 4)
knn_kernel(const float* __restrict__ q_pts,
           int n_per, int m_pairs, int bpb, int qpb) {
    __shared__ __align__(16) float4 spA[MP_MAX];
    __shared__ __align__(16) float4 spB[MP_MAX];
    int batch = blockIdx.x / bpb;
    int bb    = blockIdx.x % bpb;
    int tid = threadIdx.x;

    for (int i = tid; i < m_pairs; i += blockDim.x) {
        spA[i] = g_ptsA[batch * m_pairs + i];
        spB[i] = g_ptsB[batch * m_pairs + i];
    }
    __syncthreads();

    int off = 64 * ((blockIdx.x / 148) & 1);
    int qi  = tid - off;
    if (qi < 0 || qi >= qpb) return;
    int ql = bb * qpb + qi;
    if (ql >= n_per) return;
    int qg = batch * n_per + ql;

    float qx = q_pts[3 * qg + 0];
    float qy = q_pts[3 * qg + 1];
    float qz = q_pts[3 * qg + 2];
    float qq = sq3(qx, qy, qz);

    uint64_t qx2 = bcast2(qx), qy2 = bcast2(qy), qz2 = bcast2(qz);

    uint32_t sA = (uint32_t)__cvta_generic_to_shared(spA);
    uint32_t sB = (uint32_t)__cvta_generic_to_shared(spB);
    const float* fA = reinterpret_cast<const float*>(spA);
    const float* fB = reinterpret_cast<const float*>(spB);

    float b0v = INFINITY, b1v = INFINITY, b2v = INFINITY;
    int   b0i = 0, b1i = 0, b2i = 0;
    float thr = INFINITY;            // (b2v - qq) + slack

    // m_pairs = 1500 = 375 * 4 (exact)
#pragma unroll 1
    for (int jp0 = 0; jp0 < m_pairs; jp0 += 4) {
        float cmin;
#pragma unroll
        for (int u = 0; u < 4; u++) {
            uint32_t o16 = (uint32_t)(jp0 + u) * 16u;
            uint64_t px2, py2, pz2, pw2;
            asm("ld.shared.v2.u64 {%0, %1}, [%2];"
                : "=l"(px2), "=l"(py2) : "r"(sA + o16));
            asm("ld.shared.v2.u64 {%0, %1}, [%2];"
                : "=l"(pz2), "=l"(pw2) : "r"(sB + o16));
            uint64_t dp = fma2(qz2, pz2, fma2(qy2, py2, fma2(qx2, px2, pw2)));
            float dlo, dhi;
            unpack2(dp, dlo, dhi);
            float m = fminf(dlo, dhi);
            cmin = (u == 0) ? m : fminf(cmin, m);
        }
        if (cmin < thr) {
            // rare path: frozen bit-exact scalar d + frozen stable insert
#pragma unroll
            for (int v = 0; v < 8; v++) {
                int jp = jp0 + (v >> 1);
                int s  = v & 1;
                float pxn = fA[jp * 4 + 0 + s];
                float pyn = fA[jp * 4 + 2 + s];
                float pzn = fB[jp * 4 + 0 + s];
                float pw  = fB[jp * 4 + 2 + s];
                float dotn = __fmaf_rn(qz, pzn, __fmaf_rn(qy, pyn, __fmul_rn(qx, pxn)));
                float t    = __fadd_rn(qq, pw);
                float d    = __fadd_rn(t, dotn);   // == fsub(t, 2*dot) bitwise
                if (d < b2v) {
                    int j = jp0 * 2 + v;
                    if (d < b1v) {
                        b2v = b1v; b2i = b1i;
                        if (d < b0v) { b1v = b0v; b1i = b0i; b0v = d; b0i = j; }
                        else         { b1v = d;  b1i = j; }
                    } else {
                        b2v = d; b2i = j;
                    }
                }
            }
            thr = __fadd_rn(__fsub_rn(b2v, qq), 4e-6f);
        }
    }

    float d0 = fmaxf(b0v, 0.0f);
    float d1 = fmaxf(b1v, 0.0f);
    float d2 = fmaxf(b2v, 0.0f);
    float r0 = __fdiv_rn(1.0f, __fadd_rn(d0, 1e-8f));
    float r1 = __fdiv_rn(1.0f, __fadd_rn(d1, 1e-8f));
    float r2 = __fdiv_rn(1.0f, __fadd_rn(d2, 1e-8f));
    float s = __fadd_rn(__fadd_rn(r0, r1), r2);
    int m_per = m_pairs * 2;
    g_w[qg * 3 + 0] = __fdiv_rn(r0, s);
    g_w[qg * 3 + 1] = __fdiv_rn(r1, s);
    g_w[qg * 3 + 2] = __fdiv_rn(r2, s);
    g_idx[qg * 3 + 0] = batch * m_per + b0i;
    g_idx[qg * 3 + 1] = batch * m_per + b1i;
    g_idx[qg * 3 + 2] = batch * m_per + b2i;
}

// ---------------- exact-fp32 GEMM + fused BN/ReLU (+ gather-add) ----------
// FROZEN (round 11, at ~92% of FFMA rt=2 roofline). X[M,K] @ W[K,128];
// block tile BM x 128, 256 threads, micro-tile (BM/16) x 8, double-buffered
// smem, conflict-free B mapping {tx*4, 64+tx*4}. Sequential ascending-k fma.
template <int K, int BM, int MB, bool GATHER>
__global__ void __launch_bounds__(256, MB)
gemm_bn_relu_kernel(const float* __restrict__ X, const float* __restrict__ Wt,
                    const float* __restrict__ bb, const float* __restrict__ gg,
                    const float* __restrict__ bet, const float* __restrict__ mu,
                    const float* __restrict__ var, float* __restrict__ out,
                    int M) {
    constexpr int RPT = BM / 16;
    __shared__ __align__(16) float As[2][16][BM + 4];
    __shared__ __align__(16) float Bs[2][16][128];

    int tid = threadIdx.x;
    int tx = tid & 15;
    int ty = tid >> 4;
    int m0 = blockIdx.x * BM;

    float acc[RPT][8];
#pragma unroll
    for (int r = 0; r < RPT; r++)
#pragma unroll
        for (int c = 0; c < 8; c++) acc[r][c] = 0.0f;

    int a_row = tid >> 2;
    int a_k   = (tid & 3) * 4;
    int b_k = tid >> 5;
    int b_n = (tid & 31) * 4;

    int ar0 = m0 + a_row;       if (ar0 >= M) ar0 = M - 1;
    const float* pa0 = X + (size_t)ar0 * K + a_k;
    const float* pa1 = pa0;
    if (BM == 128) {
        int ar1 = m0 + 64 + a_row;  if (ar1 >= M) ar1 = M - 1;
        pa1 = X + (size_t)ar1 * K + a_k;
    }

    constexpr int NT = K / 16;

    float4 va0, va1, vb0, vb1;
    va0 = *reinterpret_cast<const float4*>(pa0);
    if (BM == 128) va1 = *reinterpret_cast<const float4*>(pa1);
    vb0 = *reinterpret_cast<const float4*>(&Wt[(size_t)b_k * 128 + b_n]);
    vb1 = *reinterpret_cast<const float4*>(&Wt[(size_t)(b_k + 8) * 128 + b_n]);
    {
        float av0[4] = {va0.x, va0.y, va0.z, va0.w};
#pragma unroll
        for (int i = 0; i < 4; i++) As[0][a_k + i][a_row] = av0[i];
        if (BM == 128) {
            float av1[4] = {va1.x, va1.y, va1.z, va1.w};
#pragma unroll
            for (int i = 0; i < 4; i++) As[0][a_k + i][64 + a_row] = av1[i];
        }
        *reinterpret_cast<float4*>(&Bs[0][b_k][b_n]) = vb0;
        *reinterpret_cast<float4*>(&Bs[0][b_k + 8][b_n]) = vb1;
    }
    __syncthreads();

    for (int kt = 0; kt < NT; kt++) {
        int buf = kt & 1;
        if (kt + 1 < NT) {
            int ko = (kt + 1) * 16;
            va0 = *reinterpret_cast<const float4*>(pa0 + ko);
            if (BM == 128) va1 = *reinterpret_cast<const float4*>(pa1 + ko);
            vb0 = *reinterpret_cast<const float4*>(&Wt[(size_t)(ko + b_k) * 128 + b_n]);
            vb1 = *reinterpret_cast<const float4*>(&Wt[(size_t)(ko + b_k + 8) * 128 + b_n]);
        }

#pragma unroll
        for (int kk = 0; kk < 16; kk++) {
            float av[RPT];
#pragma unroll
            for (int r = 0; r < RPT; r += 4) {
                float4 x0 = *reinterpret_cast<const float4*>(&As[buf][kk][ty * RPT + r]);
                av[r] = x0.x; av[r + 1] = x0.y; av[r + 2] = x0.z; av[r + 3] = x0.w;
            }
            float4 y0 = *reinterpret_cast<const float4*>(&Bs[buf][kk][tx * 4]);
            float4 y1 = *reinterpret_cast<const float4*>(&Bs[buf][kk][64 + tx * 4]);
            float bv[8] = {y0.x, y0.y, y0.z, y0.w, y1.x, y1.y, y1.z, y1.w};
#pragma unroll
            for (int r = 0; r < RPT; r++)
#pragma unroll
                for (int c = 0; c < 8; c++)
                    acc[r][c] = fmaf(av[r], bv[c], acc[r][c]);
        }

        if (kt + 1 < NT) {
            int nb = buf ^ 1;
            float av0[4] = {va0.x, va0.y, va0.z, va0.w};
#pragma unroll
            for (int i = 0; i < 4; i++) As[nb][a_k + i][a_row] = av0[i];
            if (BM == 128) {
                float av1[4] = {va1.x, va1.y, va1.z, va1.w};
#pragma unroll
                for (int i = 0; i < 4; i++) As[nb][a_k + i][64 + a_row] = av1[i];
            }
            *reinterpret_cast<float4*>(&Bs[nb][b_k][b_n]) = vb0;
            *reinterpret_cast<float4*>(&Bs[nb][b_k + 8][b_n]) = vb1;
            __syncthreads();
        }
    }

    int col0 = tx * 4;
    int col1 = 64 + tx * 4;
    float S[8], T[8];
#pragma unroll
    for (int c = 0; c < 8; c++) {
        int cc = (c < 4) ? (col0 + c) : (col1 + c - 4);
        float sc = gg[cc] * rsqrtf(var[cc] + 1e-5f);
        S[c] = sc;
        T[c] = fmaf(bb[cc] - mu[cc], sc, bet[cc]);
    }
#pragma unroll
    for (int r = 0; r < RPT; r++) {
        int row = m0 + ty * RPT + r;
        if (row < M) {
            float o[8];
#pragma unroll
            for (int c = 0; c < 8; c++)
                o[c] = fmaxf(fmaf(acc[r][c], S[c], T[c]), 0.0f);
            if (GATHER) {
#pragma unroll
                for (int t = 0; t < 3; t++) {
                    int id = g_idx[row * 3 + t];
                    float w = g_w[row * 3 + t];
                    const float* f = &g_f2[(size_t)id * 128];
                    float4 f0 = *reinterpret_cast<const float4*>(f + col0);
                    float4 f1 = *reinterpret_cast<const float4*>(f + col1);
                    o[0] = fmaf(w, f0.x, o[0]);
                    o[1] = fmaf(w, f0.y, o[1]);
                    o[2] = fmaf(w, f0.z, o[2]);
                    o[3] = fmaf(w, f0.w, o[3]);
                    o[4] = fmaf(w, f1.x, o[4]);
                    o[5] = fmaf(w, f1.y, o[5]);
                    o[6] = fmaf(w, f1.z, o[6]);
                    o[7] = fmaf(w, f1.w, o[7]);
                }
            }
            float4 w0 = make_float4(o[0], o[1], o[2], o[3]);
            float4 w1 = make_float4(o[4], o[5], o[6], o[7]);
            *reinterpret_cast<float4*>(&out[(size_t)row * 128 + col0]) = w0;
            *reinterpret_cast<float4*>(&out[(size_t)row * 128 + col1]) = w1;
        }
    }
}

// ---------------- launch --------------------------------------------------
extern "C" void kernel_launch(void* const* d_in, const int* in_sizes, int n_in,
                              void* d_out, int out_size) {
    const float* point1 = (const float*)d_in[0];
    const float* feat1  = (const float*)d_in[1];
    const float* point2 = (const float*)d_in[2];
    const float* feat2  = (const float*)d_in[3];
    const float* W1  = (const float*)d_in[4];
    const float* b1  = (const float*)d_in[5];
    const float* g1  = (const float*)d_in[6];
    const float* be1 = (const float*)d_in[7];
    const float* mu1 = (const float*)d_in[8];
    const float* v1  = (const float*)d_in[9];
    const float* W2  = (const float*)d_in[10];
    const float* b2  = (const float*)d_in[11];
    const float* g2  = (const float*)d_in[12];
    const float* be2 = (const float*)d_in[13];
    const float* mu2 = (const float*)d_in[14];
    const float* v2  = (const float*)d_in[15];

    int n_tot = in_sizes[0] / 3;           // 96000
    int m_tot = in_sizes[2] / 3;           // 24000
    int n_per = n_tot / B_CONST;           // 12000
    int m_pairs = (m_tot / B_CONST) / 2;   // 1500

    float* f2 = nullptr;
    cudaGetSymbolAddress((void**)&f2, g_f2);

    // 1) pack coarse points
    int tot_pairs = m_tot / 2;
    pack_pts_kernel<<<(tot_pairs + 255) / 256, 256>>>(point2, tot_pairs);

    // 2) dense2 + BN + ReLU -> g_f2   (BM=64: 375 balanced CTAs)
    gemm_bn_relu_kernel<256, 64, 3, false><<<(m_tot + 63) / 64, 256>>>(
        feat2, W2, b2, g2, be2, mu2, v2, f2, m_tot);

    // 3) exact 3-NN + IDW; 8 x 74 = 592 CTAs = 4 x 148 SMs
    int bpb = 74;
    int qpb = (n_per + bpb - 1) / bpb;     // 163
    knn_kernel<<<B_CONST * bpb, 256>>>(point1, n_per, m_pairs, bpb, qpb);

    // 4) dense1 + BN + ReLU + gather-add -> out (BM=128)
    gemm_bn_relu_kernel<128, 128, 2, true><<<(n_tot + 127) / 128, 256>>>(
        feat1, W1, b1, g1, be1, mu1, v1, (float*)d_out, n_tot);
}

// round 15
// speedup vs baseline: 1.5945x; 1.1546x over previous
#include <cuda_runtime.h>
#include <math.h>
#include <stdint.h>

// Geometry: point_1 (96000,3) feat_1 (96000,128); point_2 (24000,3)
// feat_2 (24000,256); B=8 -> 12000 queries / 3000 points per cloud.
#define B_CONST     8
#define N_TOT_MAX   96000
#define M_TOT_MAX   24000
#define OUTP        128
#define MP_MAX      1500      // point PAIRS per cloud

// ---------------- device scratch ------------------------------------------
__device__ float  g_f2[M_TOT_MAX * OUTP];
__device__ float4 g_ptsA[M_TOT_MAX / 2];   // (-2x0,-2x1,-2y0,-2y1)
__device__ float4 g_ptsB[M_TOT_MAX / 2];   // (-2z0,-2z1, pp0, pp1)
__device__ int    g_idx[N_TOT_MAX * 3];
__device__ float  g_w [N_TOT_MAX * 3];

// ---------------- frozen numerics (bit-exact vs reference) ----------------
__device__ __forceinline__ float sq3(float x, float y, float z) {
    return __fmaf_rn(x, x, __fmaf_rn(y, y, __fmul_rn(z, z)));
}

// ---------------- packed f32x2 helpers ------------------------------------
__device__ __forceinline__ uint64_t bcast2(float v) {
    uint64_t r; uint32_t u = __float_as_uint(v);
    asm("mov.b64 %0, {%1, %1};" : "=l"(r) : "r"(u));
    return r;
}
__device__ __forceinline__ uint64_t mul2(uint64_t a, uint64_t b) {
    uint64_t d; asm("mul.rn.f32x2 %0, %1, %2;" : "=l"(d) : "l"(a), "l"(b));
    return d;
}
__device__ __forceinline__ uint64_t fma2(uint64_t a, uint64_t b, uint64_t c) {
    uint64_t d; asm("fma.rn.f32x2 %0, %1, %2, %3;" : "=l"(d) : "l"(a), "l"(b), "l"(c));
    return d;
}
__device__ __forceinline__ uint64_t add2(uint64_t a, uint64_t b) {
    uint64_t d; asm("add.rn.f32x2 %0, %1, %2;" : "=l"(d) : "l"(a), "l"(b));
    return d;
}
__device__ __forceinline__ void unpack2(uint64_t v, float& lo, float& hi) {
    asm("mov.b64 {%0, %1}, %2;" : "=f"(lo), "=f"(hi) : "l"(v));
}

// ---------------- pack points (negated-doubled pair layout) ---------------
__global__ void pack_pts_kernel(const float* __restrict__ p2, int m_pairs) {
    int i = blockIdx.x * blockDim.x + threadIdx.x;
    if (i < m_pairs) {
        float x0 = p2[6 * i + 0], y0 = p2[6 * i + 1], z0 = p2[6 * i + 2];
        float x1 = p2[6 * i + 3], y1 = p2[6 * i + 4], z1 = p2[6 * i + 5];
        g_ptsA[i] = make_float4(-2.0f * x0, -2.0f * x1, -2.0f * y0, -2.0f * y1);
        g_ptsB[i] = make_float4(-2.0f * z0, -2.0f * z1, sq3(x0, y0, z0), sq3(x1, y1, z1));
    }
}

// ---------------- exact 3-NN + IDW (f32x2) --------------------------------
// Hot loop and selection BYTE-IDENTICAL to the round-11 passing kernel
// (262.4us, rel_err 9.417942e-4). Only the GRID changed: 47 blocks/batch x
// 256 queries/block -> all 8 warps active = exactly 2 warps per SMSP,
// removing the (2,2,1,1) SMSP imbalance of the 163-query config (SMSP0
// carried 8 warp-loops; now worst case is 6 with 3 resident CTAs).
__global__ void __launch_bounds__(256, 4)
knn_kernel(const float* __restrict__ q_pts,
           int n_per, int m_pairs, int bpb, int qpb) {
    __shared__ __align__(16) float4 spA[MP_MAX];
    __shared__ __align__(16) float4 spB[MP_MAX];
    int batch = blockIdx.x / bpb;
    int bb    = blockIdx.x % bpb;
    int tid = threadIdx.x;

    for (int i = tid; i < m_pairs; i += blockDim.x) {
        spA[i] = g_ptsA[batch * m_pairs + i];
        spB[i] = g_ptsB[batch * m_pairs + i];
    }
    __syncthreads();

    int ql = bb * qpb + tid;
    if (tid >= qpb || ql >= n_per) return;
    int qg = batch * n_per + ql;

    float qx = q_pts[3 * qg + 0];
    float qy = q_pts[3 * qg + 1];
    float qz = q_pts[3 * qg + 2];
    float qq = sq3(qx, qy, qz);

    uint64_t qx2 = bcast2(qx), qy2 = bcast2(qy), qz2 = bcast2(qz);
    uint64_t qq2 = bcast2(qq);

    uint32_t sA = (uint32_t)__cvta_generic_to_shared(spA);
    uint32_t sB = (uint32_t)__cvta_generic_to_shared(spB);

    float b0v = INFINITY, b1v = INFINITY, b2v = INFINITY;
    int   b0i = 0, b1i = 0, b2i = 0;

    // m_pairs = 1500 = 375 * 4 (exact)
#pragma unroll 1
    for (int jp0 = 0; jp0 < m_pairs; jp0 += 4) {
        float dv[8];
        float cmin;
#pragma unroll
        for (int u = 0; u < 4; u++) {
            uint32_t off = (uint32_t)(jp0 + u) * 16u;
            uint64_t px2, py2, pz2, pw2;
            asm("ld.shared.v2.u64 {%0, %1}, [%2];"
                : "=l"(px2), "=l"(py2) : "r"(sA + off));
            asm("ld.shared.v2.u64 {%0, %1}, [%2];"
                : "=l"(pz2), "=l"(pw2) : "r"(sB + off));
            uint64_t dotn = fma2(qz2, pz2, fma2(qy2, py2, mul2(qx2, px2)));
            uint64_t t    = add2(qq2, pw2);
            uint64_t d    = add2(t, dotn);
            float dlo, dhi;
            unpack2(d, dlo, dhi);
            dv[2 * u]     = dlo;
            dv[2 * u + 1] = dhi;
            float m = fminf(dlo, dhi);
            cmin = (u == 0) ? m : fminf(cmin, m);
        }
        if (cmin < b2v) {
#pragma unroll
            for (int v = 0; v < 8; v++) {
                float d = dv[v];
                if (d < b2v) {
                    int j = jp0 * 2 + v;
                    if (d < b1v) {
                        b2v = b1v; b2i = b1i;
                        if (d < b0v) { b1v = b0v; b1i = b0i; b0v = d; b0i = j; }
                        else         { b1v = d;  b1i = j; }
                    } else {
                        b2v = d; b2i = j;
                    }
                }
            }
        }
    }

    float d0 = fmaxf(b0v, 0.0f);
    float d1 = fmaxf(b1v, 0.0f);
    float d2 = fmaxf(b2v, 0.0f);
    float r0 = __fdiv_rn(1.0f, __fadd_rn(d0, 1e-8f));
    float r1 = __fdiv_rn(1.0f, __fadd_rn(d1, 1e-8f));
    float r2 = __fdiv_rn(1.0f, __fadd_rn(d2, 1e-8f));
    float s = __fadd_rn(__fadd_rn(r0, r1), r2);
    int m_per = m_pairs * 2;
    g_w[qg * 3 + 0] = __fdiv_rn(r0, s);
    g_w[qg * 3 + 1] = __fdiv_rn(r1, s);
    g_w[qg * 3 + 2] = __fdiv_rn(r2, s);
    g_idx[qg * 3 + 0] = batch * m_per + b0i;
    g_idx[qg * 3 + 1] = batch * m_per + b1i;
    g_idx[qg * 3 + 2] = batch * m_per + b2i;
}

// ---------------- exact-fp32 GEMM + fused BN/ReLU (+ gather-add) ----------
// FROZEN (round 11, ~92% of FFMA rt=2 roofline). X[M,K] @ W[K,128];
// block tile BM x 128, 256 threads, micro-tile (BM/16) x 8, double-buffered
// smem, conflict-free B mapping {tx*4, 64+tx*4}. Sequential ascending-k fma.
// BM=128 for gemm1; BM=64 for gemm2 (375 balanced CTAs).
template <int K, int BM, int MB, bool GATHER>
__global__ void __launch_bounds__(256, MB)
gemm_bn_relu_kernel(const float* __restrict__ X, const float* __restrict__ Wt,
                    const float* __restrict__ bb, const float* __restrict__ gg,
                    const float* __restrict__ bet, const float* __restrict__ mu,
                    const float* __restrict__ var, float* __restrict__ out,
                    int M) {
    constexpr int RPT = BM / 16;
    __shared__ __align__(16) float As[2][16][BM + 4];
    __shared__ __align__(16) float Bs[2][16][128];

    int tid = threadIdx.x;
    int tx = tid & 15;
    int ty = tid >> 4;
    int m0 = blockIdx.x * BM;

    float acc[RPT][8];
#pragma unroll
    for (int r = 0; r < RPT; r++)
#pragma unroll
        for (int c = 0; c < 8; c++) acc[r][c] = 0.0f;

    int a_row = tid >> 2;
    int a_k   = (tid & 3) * 4;
    int b_k = tid >> 5;
    int b_n = (tid & 31) * 4;

    int ar0 = m0 + a_row;       if (ar0 >= M) ar0 = M - 1;
    const float* pa0 = X + (size_t)ar0 * K + a_k;
    const float* pa1 = pa0;
    if (BM == 128) {
        int ar1 = m0 + 64 + a_row;  if (ar1 >= M) ar1 = M - 1;
        pa1 = X + (size_t)ar1 * K + a_k;
    }

    constexpr int NT = K / 16;

    float4 va0, va1, vb0, vb1;
    va0 = *reinterpret_cast<const float4*>(pa0);
    if (BM == 128) va1 = *reinterpret_cast<const float4*>(pa1);
    vb0 = *reinterpret_cast<const float4*>(&Wt[(size_t)b_k * 128 + b_n]);
    vb1 = *reinterpret_cast<const float4*>(&Wt[(size_t)(b_k + 8) * 128 + b_n]);
    {
        float av0[4] = {va0.x, va0.y, va0.z, va0.w};
#pragma unroll
        for (int i = 0; i < 4; i++) As[0][a_k + i][a_row] = av0[i];
        if (BM == 128) {
            float av1[4] = {va1.x, va1.y, va1.z, va1.w};
#pragma unroll
            for (int i = 0; i < 4; i++) As[0][a_k + i][64 + a_row] = av1[i];
        }
        *reinterpret_cast<float4*>(&Bs[0][b_k][b_n]) = vb0;
        *reinterpret_cast<float4*>(&Bs[0][b_k + 8][b_n]) = vb1;
    }
    __syncthreads();

    for (int kt = 0; kt < NT; kt++) {
        int buf = kt & 1;
        if (kt + 1 < NT) {
            int ko = (kt + 1) * 16;
            va0 = *reinterpret_cast<const float4*>(pa0 + ko);
            if (BM == 128) va1 = *reinterpret_cast<const float4*>(pa1 + ko);
            vb0 = *reinterpret_cast<const float4*>(&Wt[(size_t)(ko + b_k) * 128 + b_n]);
            vb1 = *reinterpret_cast<const float4*>(&Wt[(size_t)(ko + b_k + 8) * 128 + b_n]);
        }

#pragma unroll
        for (int kk = 0; kk < 16; kk++) {
            float av[RPT];
#pragma unroll
            for (int r = 0; r < RPT; r += 4) {
                float4 x0 = *reinterpret_cast<const float4*>(&As[buf][kk][ty * RPT + r]);
                av[r] = x0.x; av[r + 1] = x0.y; av[r + 2] = x0.z; av[r + 3] = x0.w;
            }
            float4 y0 = *reinterpret_cast<const float4*>(&Bs[buf][kk][tx * 4]);
            float4 y1 = *reinterpret_cast<const float4*>(&Bs[buf][kk][64 + tx * 4]);
            float bv[8] = {y0.x, y0.y, y0.z, y0.w, y1.x, y1.y, y1.z, y1.w};
#pragma unroll
            for (int r = 0; r < RPT; r++)
#pragma unroll
                for (int c = 0; c < 8; c++)
                    acc[r][c] = fmaf(av[r], bv[c], acc[r][c]);
        }

        if (kt + 1 < NT) {
            int nb = buf ^ 1;
            float av0[4] = {va0.x, va0.y, va0.z, va0.w};
#pragma unroll
            for (int i = 0; i < 4; i++) As[nb][a_k + i][a_row] = av0[i];
            if (BM == 128) {
                float av1[4] = {va1.x, va1.y, va1.z, va1.w};
#pragma unroll
                for (int i = 0; i < 4; i++) As[nb][a_k + i][64 + a_row] = av1[i];
            }
            *reinterpret_cast<float4*>(&Bs[nb][b_k][b_n]) = vb0;
            *reinterpret_cast<float4*>(&Bs[nb][b_k + 8][b_n]) = vb1;
            __syncthreads();
        }
    }

    int col0 = tx * 4;
    int col1 = 64 + tx * 4;
    float S[8], T[8];
#pragma unroll
    for (int c = 0; c < 8; c++) {
        int cc = (c < 4) ? (col0 + c) : (col1 + c - 4);
        float sc = gg[cc] * rsqrtf(var[cc] + 1e-5f);
        S[c] = sc;
        T[c] = fmaf(bb[cc] - mu[cc], sc, bet[cc]);
    }
#pragma unroll
    for (int r = 0; r < RPT; r++) {
        int row = m0 + ty * RPT + r;
        if (row < M) {
            float o[8];
#pragma unroll
            for (int c = 0; c < 8; c++)
                o[c] = fmaxf(fmaf(acc[r][c], S[c], T[c]), 0.0f);
            if (GATHER) {
#pragma unroll
                for (int t = 0; t < 3; t++) {
                    int id = g_idx[row * 3 + t];
                    float w = g_w[row * 3 + t];
                    const float* f = &g_f2[(size_t)id * 128];
                    float4 f0 = *reinterpret_cast<const float4*>(f + col0);
                    float4 f1 = *reinterpret_cast<const float4*>(f + col1);
                    o[0] = fmaf(w, f0.x, o[0]);
                    o[1] = fmaf(w, f0.y, o[1]);
                    o[2] = fmaf(w, f0.z, o[2]);
                    o[3] = fmaf(w, f0.w, o[3]);
                    o[4] = fmaf(w, f1.x, o[4]);
                    o[5] = fmaf(w, f1.y, o[5]);
                    o[6] = fmaf(w, f1.z, o[6]);
                    o[7] = fmaf(w, f1.w, o[7]);
                }
            }
            float4 w0 = make_float4(o[0], o[1], o[2], o[3]);
            float4 w1 = make_float4(o[4], o[5], o[6], o[7]);
            *reinterpret_cast<float4*>(&out[(size_t)row * 128 + col0]) = w0;
            *reinterpret_cast<float4*>(&out[(size_t)row * 128 + col1]) = w1;
        }
    }
}

// ---------------- launch --------------------------------------------------
extern "C" void kernel_launch(void* const* d_in, const int* in_sizes, int n_in,
                              void* d_out, int out_size) {
    const float* point1 = (const float*)d_in[0];
    const float* feat1  = (const float*)d_in[1];
    const float* point2 = (const float*)d_in[2];
    const float* feat2  = (const float*)d_in[3];
    const float* W1  = (const float*)d_in[4];
    const float* b1  = (const float*)d_in[5];
    const float* g1  = (const float*)d_in[6];
    const float* be1 = (const float*)d_in[7];
    const float* mu1 = (const float*)d_in[8];
    const float* v1  = (const float*)d_in[9];
    const float* W2  = (const float*)d_in[10];
    const float* b2  = (const float*)d_in[11];
    const float* g2  = (const float*)d_in[12];
    const float* be2 = (const float*)d_in[13];
    const float* mu2 = (const float*)d_in[14];
    const float* v2  = (const float*)d_in[15];

    int n_tot = in_sizes[0] / 3;           // 96000
    int m_tot = in_sizes[2] / 3;           // 24000
    int n_per = n_tot / B_CONST;           // 12000
    int m_pairs = (m_tot / B_CONST) / 2;   // 1500

    float* f2 = nullptr;
    cudaGetSymbolAddress((void**)&f2, g_f2);

    // 1) pack coarse points
    int tot_pairs = m_tot / 2;
    pack_pts_kernel<<<(tot_pairs + 255) / 256, 256>>>(point2, tot_pairs);

    // 2) dense2 + BN + ReLU -> g_f2   (BM=64: 375 balanced CTAs)
    gemm_bn_relu_kernel<256, 64, 3, false><<<(m_tot + 63) / 64, 256>>>(
        feat2, W2, b2, g2, be2, mu2, v2, f2, m_tot);

    // 3) exact 3-NN + IDW; 8 x 47 blocks, 256 q/block -> 8 warps = 2/SMSP
    int bpb = 47, qpb = 256;
    knn_kernel<<<B_CONST * bpb, 256>>>(point1, n_per, m_pairs, bpb, qpb);

    // 4) dense1 + BN + ReLU + gather-add -> out (BM=128)
    gemm_bn_relu_kernel<128, 128, 2, true><<<(n_tot + 127) / 128, 256>>>(
        feat1, W1, b1, g1, be1, mu1, v1, (float*)d_out, n_tot);
}